// round 3
// baseline (speedup 1.0000x reference)
#include <cuda_runtime.h>
#include <math.h>

// Problem-fixed shapes
#define H   4096
#define W   4096
#define W2  8192

#define SCONST       1e-12f
#define EPS_V_FLOOR  (1e-32f / 6.0f)

#define TILE_I 32
#define TILE_J 32
#define SM_W   36            // TILE + 2*halo
#define NBLK_I (H / TILE_I)  // 128
#define NBLK_J (W / TILE_J)  // 128

__device__ double g_partials[NBLK_I * NBLK_J];

__device__ __forceinline__ float warp_reduce_f(float v) {
#pragma unroll
    for (int o = 16; o > 0; o >>= 1)
        v += __shfl_xor_sync(0xffffffffu, v, o);
    return v;
}

__global__ __launch_bounds__(256, 4)
void curve_kernel(const float* __restrict__ eps, const float* __restrict__ gs) {
    __shared__ float tile[SM_W * SM_W];
    __shared__ double warp_part[8];

    const float d   = *gs;
    const float rd  = 1.0f / d;
    const float r2d = 0.5f / d;
    const float r2d2 = r2d * r2d;
    const float pi_d = 3.14159265358979323846f / 1.1f;

    const int tx  = threadIdx.x;           // 0..31 (j)
    const int ty  = threadIdx.y;           // 0..7  (i group)
    const int tid = ty * 32 + tx;
    const int bi0 = blockIdx.y * TILE_I;
    const int bj0 = blockIdx.x * TILE_J;

    // Cooperative load of (TILE+4)x(TILE+4) halo tile.
    // Rows are clamped (clamped rows are never read by the compute below);
    // columns >= W use the mirror map of the reference's concatenated field.
    for (int idx = tid; idx < SM_W * SM_W; idx += 256) {
        int r  = idx / SM_W;
        int cl = idx - r * SM_W;
        int gi = bi0 - 2 + r;
        gi = gi < 0 ? 0 : (gi > H - 1 ? H - 1 : gi);
        int gj = bj0 - 2 + cl;
        gj = gj < 0 ? 0 : (gj < W ? gj : (W2 - 1 - gj));
        tile[idx] = eps[gi * W + gj];
    }
    __syncthreads();

#define S(a, b) tile[(a) * SM_W + (b)]

    float acc = 0.0f;

#pragma unroll
    for (int rr = 0; rr < 4; rr++) {
        const int li = ty + rr * 8;
        const int i  = bi0 + li;
        const int j  = bj0 + tx;
        const int si = li + 2;
        const int sj = tx + 2;

        const float c = S(si, sj);
        float ex, ey, exx, exy, eyy;

        if (i >= 2 && i <= H - 3 && j >= 2) {
            // Fast interior path: pure central differences (the column mirror
            // beyond the seam is already baked into the shared tile).
            const float xp1 = S(si + 1, sj), xm1 = S(si - 1, sj);
            const float xp2 = S(si + 2, sj), xm2 = S(si - 2, sj);
            const float yp1 = S(si, sj + 1), ym1 = S(si, sj - 1);
            const float yp2 = S(si, sj + 2), ym2 = S(si, sj - 2);
            const float dpp = S(si + 1, sj + 1), dpm = S(si + 1, sj - 1);
            const float dmp = S(si - 1, sj + 1), dmm = S(si - 1, sj - 1);
            ex  = (xp1 - xm1) * r2d;
            ey  = (yp1 - ym1) * r2d;
            exx = (xp2 - 2.0f * c + xm2) * r2d2;
            eyy = (yp2 - 2.0f * c + ym2) * r2d2;
            exy = ((dpp - dmp) - (dpm - dmm)) * r2d2;
        } else {
            // Boundary path: replicate composed boundary-flavored operators.
            auto EXf = [&](int gi_, int a, int b) -> float {
                if (gi_ == 0)     return (S(a + 1, b) - S(a, b)) * rd;
                if (gi_ == H - 1) return (S(a, b) - S(a - 1, b)) * rd;
                return (S(a + 1, b) - S(a - 1, b)) * r2d;
            };
            auto EYf = [&](int gj_, int a, int b) -> float {
                if (gj_ == 0) return (S(a, b + 1) - S(a, b)) * rd;
                return (S(a, b + 1) - S(a, b - 1)) * r2d;  // gj_==W2-1 unreachable for j<W
            };
            ex = EXf(i, si, sj);
            ey = EYf(j, si, sj);
            if (i == 0)
                exx = (EXf(1, si + 1, sj) - EXf(0, si, sj)) * rd;
            else if (i == H - 1)
                exx = (EXf(H - 1, si, sj) - EXf(H - 2, si - 1, sj)) * rd;
            else
                exx = (EXf(i + 1, si + 1, sj) - EXf(i - 1, si - 1, sj)) * r2d;
            if (j == 0) {
                exy = (EXf(i, si, sj + 1) - EXf(i, si, sj)) * rd;
                eyy = (EYf(1, si, sj + 1) - EYf(0, si, sj)) * rd;
            } else {
                exy = (EXf(i, si, sj + 1) - EXf(i, si, sj - 1)) * r2d;
                eyy = (EYf(j + 1, si, sj + 1) - EYf(j - 1, si, sj - 1)) * r2d;
            }
        }

        const float exs = ex + SCONST;
        const float eys = ey + SCONST;
        const float ev2 = exs * exs + eys * eys;
        float ev = sqrtf(ev2);
        ev = fmaxf(ev, EPS_V_FLOOR);
        const float num = exs * exs * eyy - 2.0f * exs * eys * exy + eys * eys * exx;
        const float k   = num / (ev * ev * ev);
        const float t   = atanf(ev / c);
        const float val = fmaxf(fabsf(k * t) - pi_d, 0.0f);  // fmaxf(NaN,0)=0 == nansum drop
        acc += val;
    }

#undef S

    const float wsum = warp_reduce_f(acc);
    if ((tid & 31) == 0) warp_part[tid >> 5] = (double)wsum;
    __syncthreads();
    if (tid == 0) {
        double s = 0.0;
#pragma unroll
        for (int w = 0; w < 8; w++) s += warp_part[w];
        g_partials[blockIdx.y * NBLK_J + blockIdx.x] = s;
    }
}

__global__ __launch_bounds__(256)
void reduce_kernel(float* __restrict__ out, const float* __restrict__ gs) {
    __shared__ double sm[256];
    double s = 0.0;
    for (int idx = threadIdx.x; idx < NBLK_I * NBLK_J; idx += 256)
        s += g_partials[idx];
    sm[threadIdx.x] = s;
    __syncthreads();
    for (int off = 128; off > 0; off >>= 1) {
        if (threadIdx.x < off) sm[threadIdx.x] += sm[threadIdx.x + off];
        __syncthreads();
    }
    if (threadIdx.x == 0) {
        const float d = *gs;
        // x2: mirror-symmetric halves contribute identically; ALPHA = 1
        out[0] = (float)(sm[0] * 2.0 * (double)d * (double)d);
    }
}

extern "C" void kernel_launch(void* const* d_in, const int* in_sizes, int n_in,
                              void* d_out, int out_size) {
    const float* eps = (const float*)d_in[0];
    const float* gs  = (const float*)d_in[1];
    float* out = (float*)d_out;

    dim3 grid(NBLK_J, NBLK_I);
    dim3 block(32, 8);
    curve_kernel<<<grid, block>>>(eps, gs);
    reduce_kernel<<<1, 256>>>(out, gs);
}